// round 1
// baseline (speedup 1.0000x reference)
#include <cuda_runtime.h>
#include <math.h>

#define B_SEQ   2048
#define D_DIM   128
#define H_DIM   128
#define G3      384            // 3*H
#define MAX_LEN 200
#define MAX_T   (B_SEQ * (MAX_LEN - 1))   // 407552 worst-case tokens

// Scratch for input projections x @ W_ih^T  : [T, 3H] fp32
__device__ float g_xproj[(size_t)MAX_T * G3];
// Normalized int32 offsets (handles int32 vs int64 input dtype)
__device__ int   g_off[B_SEQ];

// ---------------------------------------------------------------------------
// Offset normalization: detect whether the offset buffer is int32 or int64.
// int64 data viewed as int32 is [o0,0,o1,0,...]; since o1>0 and offsets are
// nondecreasing, an int32-view monotonicity break in the first entries means
// the data is int64. True int32 offsets are strictly increasing (lengths>=1).
// ---------------------------------------------------------------------------
__global__ void offsets_kernel(const void* __restrict__ off_raw) {
    __shared__ int is64;
    const int* v32 = (const int*)off_raw;
    if (threadIdx.x == 0) {
        int f = 0;
        #pragma unroll
        for (int i = 0; i < 31; ++i) {
            if (v32[i + 1] < v32[i]) f = 1;
        }
        is64 = f;
    }
    __syncthreads();
    int gid = blockIdx.x * blockDim.x + threadIdx.x;
    if (gid < B_SEQ) {
        if (is64) {
            const long long* v64 = (const long long*)off_raw;
            g_off[gid] = (int)v64[gid];
        } else {
            g_off[gid] = v32[gid];
        }
    }
}

// ---------------------------------------------------------------------------
// Kernel 1: x_proj[t, j] = dot(W_ih[j, :], x[t, :])   for j in [0, 384)
// 384 threads/block; thread j holds W_ih row j in 128 registers.
// 64-token x tile staged in shared; broadcast reads, FMA-pipe bound.
// ---------------------------------------------------------------------------
__global__ __launch_bounds__(384, 1)
void xproj_kernel(const float* __restrict__ x,
                  const float* __restrict__ W_ih, int T) {
    __shared__ float sx[64 * 128];
    const int j = threadIdx.x;

    float w[128];
    {
        const float4* wr = reinterpret_cast<const float4*>(W_ih) + j * 32;
        #pragma unroll
        for (int k = 0; k < 32; ++k) {
            float4 v = wr[k];
            w[4*k+0] = v.x; w[4*k+1] = v.y; w[4*k+2] = v.z; w[4*k+3] = v.w;
        }
    }

    const int t0 = blockIdx.x * 64;
    const int ntok = min(64, T - t0);
    if (ntok <= 0) return;

    const float4* xg = reinterpret_cast<const float4*>(x + (size_t)t0 * D_DIM);
    float4* sx4 = reinterpret_cast<float4*>(sx);
    for (int i = j; i < ntok * 32; i += 384) sx4[i] = xg[i];
    __syncthreads();

    float* outp = g_xproj + (size_t)t0 * G3 + j;
    for (int t = 0; t < ntok; ++t) {
        const float4* hv = reinterpret_cast<const float4*>(sx + t * D_DIM);
        float a0 = 0.f, a1 = 0.f, a2 = 0.f, a3 = 0.f;
        #pragma unroll
        for (int k = 0; k < 32; ++k) {
            float4 h4 = hv[k];
            a0 = fmaf(w[4*k+0], h4.x, a0);
            a1 = fmaf(w[4*k+1], h4.y, a1);
            a2 = fmaf(w[4*k+2], h4.z, a2);
            a3 = fmaf(w[4*k+3], h4.w, a3);
        }
        outp[(size_t)t * G3] = (a0 + a1) + (a2 + a3);
    }
}

// ---------------------------------------------------------------------------
// Kernel 2: ragged GRU recurrence, one block per sequence, 384 threads.
// Thread j holds W_hh row j in 128 registers. Fused dense + L2-normalize.
// ---------------------------------------------------------------------------
__global__ __launch_bounds__(384, 1)
void gru_kernel(const float* __restrict__ W_hh,
                const float* __restrict__ W_dense,
                const float* __restrict__ b_dense,
                float* __restrict__ out, int T) {
    const int b = blockIdx.x;
    const int j = threadIdx.x;

    __shared__ float sh_h[128];     // hidden state
    __shared__ float sh_a[384];     // xg + hg pre-activations
    __shared__ float sh_hgn[128];   // hg for the n-gate (needed separately)
    __shared__ float sh_red[4];
    __shared__ float sh_inv;

    float w[128];
    {
        const float4* wr = reinterpret_cast<const float4*>(W_hh) + j * 32;
        #pragma unroll
        for (int k = 0; k < 32; ++k) {
            float4 v = wr[k];
            w[4*k+0] = v.x; w[4*k+1] = v.y; w[4*k+2] = v.z; w[4*k+3] = v.w;
        }
    }

    const int off = g_off[b];
    const int end = (b == B_SEQ - 1) ? T : g_off[b + 1];
    const int len = end - off;

    if (j < 128) sh_h[j] = 0.f;
    __syncthreads();

    const float* xgp = g_xproj + (size_t)off * G3 + j;

    for (int t = 0; t < len; ++t) {
        // prefetch x-projection for this step (independent of h)
        float xg = xgp[(size_t)t * G3];

        // hg_j = dot(W_hh[j,:], h)
        const float4* hv = reinterpret_cast<const float4*>(sh_h);
        float a0 = 0.f, a1 = 0.f, a2 = 0.f, a3 = 0.f;
        #pragma unroll
        for (int k = 0; k < 32; ++k) {
            float4 h4 = hv[k];
            a0 = fmaf(w[4*k+0], h4.x, a0);
            a1 = fmaf(w[4*k+1], h4.y, a1);
            a2 = fmaf(w[4*k+2], h4.z, a2);
            a3 = fmaf(w[4*k+3], h4.w, a3);
        }
        float hg = (a0 + a1) + (a2 + a3);

        sh_a[j] = xg + hg;
        if (j >= 256) sh_hgn[j - 256] = hg;
        __syncthreads();

        if (j < 128) {
            float r = 1.f / (1.f + expf(-sh_a[j]));
            float z = 1.f / (1.f + expf(-sh_a[j + 128]));
            // n = tanh(xg_n + r*hg_n) = tanh((xg_n + hg_n) + (r-1)*hg_n)
            float n = tanhf(sh_a[j + 256] + (r - 1.f) * sh_hgn[j]);
            sh_h[j] = (1.f - z) * n + z * sh_h[j];
        }
        __syncthreads();
    }

    // dense: v_j = dot(W_dense[j,:], h) + b_dense[j]
    float v = 0.f;
    if (j < 128) {
        const float4* wd = reinterpret_cast<const float4*>(W_dense) + j * 32;
        const float4* hv = reinterpret_cast<const float4*>(sh_h);
        float a0 = 0.f, a1 = 0.f, a2 = 0.f, a3 = 0.f;
        #pragma unroll
        for (int k = 0; k < 32; ++k) {
            float4 wv = wd[k];
            float4 h4 = hv[k];
            a0 = fmaf(wv.x, h4.x, a0);
            a1 = fmaf(wv.y, h4.y, a1);
            a2 = fmaf(wv.z, h4.z, a2);
            a3 = fmaf(wv.w, h4.w, a3);
        }
        v = (a0 + a1) + (a2 + a3) + b_dense[j];
        float s = v * v;
        #pragma unroll
        for (int d = 16; d > 0; d >>= 1)
            s += __shfl_xor_sync(0xffffffffu, s, d);
        if ((j & 31) == 0) sh_red[j >> 5] = s;
    }
    __syncthreads();
    if (j == 0) {
        float ss = sh_red[0] + sh_red[1] + sh_red[2] + sh_red[3];
        float nrm = fmaxf(sqrtf(ss), 1e-12f);
        sh_inv = 1.f / nrm;
    }
    __syncthreads();
    if (j < 128) out[(size_t)b * D_DIM + j] = v * sh_inv;
}

// ---------------------------------------------------------------------------
extern "C" void kernel_launch(void* const* d_in, const int* in_sizes, int n_in,
                              void* d_out, int out_size) {
    const float* x       = (const float*)d_in[0];
    const void*  off_raw = d_in[1];
    const float* W_ih    = (const float*)d_in[2];
    const float* W_hh    = (const float*)d_in[3];
    const float* W_dense = (const float*)d_in[4];
    const float* b_dense = (const float*)d_in[5];
    float* out = (float*)d_out;

    const int T = in_sizes[0] / D_DIM;

    offsets_kernel<<<2, 1024>>>(off_raw);

    const int nb = (T + 63) / 64;
    xproj_kernel<<<nb, 384>>>(x, W_ih, T);

    gru_kernel<<<B_SEQ, 384>>>(W_hh, W_dense, b_dense, out, T);
}

// round 2
// speedup vs baseline: 1.1274x; 1.1274x over previous
#include <cuda_runtime.h>
#include <math.h>

#define B_SEQ   2048
#define D_DIM   128
#define H_DIM   128
#define G3      384            // 3*H
#define MAX_LEN 200
#define MAX_T   (B_SEQ * (MAX_LEN - 1))   // 407552 worst-case tokens

// Scratch for input projections x @ W_ih^T  : [T, 3H] fp32
__device__ float g_xproj[(size_t)MAX_T * G3];
// Normalized int32 offsets (handles int32 vs int64 input dtype)
__device__ int   g_off[B_SEQ];

// packed fp32x2 FMA: d = a*b + d   (Blackwell packed fp32 pipe, 2 FMA/instr)
__device__ __forceinline__ void ffma2(unsigned long long& d,
                                      unsigned long long a,
                                      unsigned long long b) {
    asm volatile("fma.rn.f32x2 %0, %1, %2, %0;" : "+l"(d) : "l"(a), "l"(b));
}
__device__ __forceinline__ float unpack_sum(unsigned long long v) {
    unsigned int lo, hi;
    asm("mov.b64 {%0,%1}, %2;" : "=r"(lo), "=r"(hi) : "l"(v));
    return __uint_as_float(lo) + __uint_as_float(hi);
}

// ---------------------------------------------------------------------------
// Offset normalization (int32 vs int64 input dtype autodetect).
// ---------------------------------------------------------------------------
__global__ void offsets_kernel(const void* __restrict__ off_raw) {
    __shared__ int is64;
    const int* v32 = (const int*)off_raw;
    if (threadIdx.x == 0) {
        int f = 0;
        #pragma unroll
        for (int i = 0; i < 31; ++i) {
            if (v32[i + 1] < v32[i]) f = 1;
        }
        is64 = f;
    }
    __syncthreads();
    int gid = blockIdx.x * blockDim.x + threadIdx.x;
    if (gid < B_SEQ) {
        if (is64) {
            const long long* v64 = (const long long*)off_raw;
            g_off[gid] = (int)v64[gid];
        } else {
            g_off[gid] = v32[gid];
        }
    }
}

// ---------------------------------------------------------------------------
// Kernel 1: x_proj[t, j] = dot(W_ih[j, :], x[t, :])   for j in [0, 384)
// 384 threads/block; thread j holds W_ih row j as 64 packed f32x2 registers.
// 96-token x tile staged in shared (48KB); packed-FMA-pipe bound.
// ---------------------------------------------------------------------------
#define XTILE 96
__global__ __launch_bounds__(384, 1)
void xproj_kernel(const float* __restrict__ x,
                  const float* __restrict__ W_ih, int T) {
    __shared__ __align__(16) float sx[XTILE * 128];
    const int j = threadIdx.x;

    unsigned long long w2[64];
    {
        const ulonglong2* wr =
            reinterpret_cast<const ulonglong2*>(W_ih + (size_t)j * 128);
        #pragma unroll
        for (int k = 0; k < 32; ++k) {
            ulonglong2 v = wr[k];
            w2[2*k]   = v.x;
            w2[2*k+1] = v.y;
        }
    }

    const int t0 = blockIdx.x * XTILE;
    const int ntok = min(XTILE, T - t0);
    if (ntok <= 0) return;

    const float4* xg = reinterpret_cast<const float4*>(x + (size_t)t0 * D_DIM);
    float4* sx4 = reinterpret_cast<float4*>(sx);
    for (int i = j; i < ntok * 32; i += 384) sx4[i] = xg[i];
    __syncthreads();

    float* outp = g_xproj + (size_t)t0 * G3 + j;
    for (int t = 0; t < ntok; ++t) {
        const ulonglong2* hv =
            reinterpret_cast<const ulonglong2*>(sx + t * D_DIM);
        unsigned long long a0 = 0ull, a1 = 0ull, a2 = 0ull, a3 = 0ull;
        #pragma unroll
        for (int k = 0; k < 16; ++k) {
            ulonglong2 h0 = hv[2*k];
            ulonglong2 h1 = hv[2*k+1];
            ffma2(a0, w2[4*k+0], h0.x);
            ffma2(a1, w2[4*k+1], h0.y);
            ffma2(a2, w2[4*k+2], h1.x);
            ffma2(a3, w2[4*k+3], h1.y);
        }
        outp[(size_t)t * G3] =
            (unpack_sum(a0) + unpack_sum(a1)) + (unpack_sum(a2) + unpack_sum(a3));
    }
}

// ---------------------------------------------------------------------------
// Kernel 2: ragged GRU recurrence, one block per sequence, 384 threads.
// Thread j holds W_hh row j as 64 packed f32x2 regs. Fused dense + normalize.
// ---------------------------------------------------------------------------
__global__ __launch_bounds__(384, 1)
void gru_kernel(const float* __restrict__ W_hh,
                const float* __restrict__ W_dense,
                const float* __restrict__ b_dense,
                float* __restrict__ out, int T) {
    const int b = blockIdx.x;
    const int j = threadIdx.x;

    __shared__ __align__(16) float sh_h[128];     // hidden state
    __shared__ float sh_a[384];                   // xg + hg pre-activations
    __shared__ float sh_hgn[128];                 // hg for the n-gate
    __shared__ float sh_red[4];
    __shared__ float sh_inv;

    unsigned long long w2[64];
    {
        const ulonglong2* wr =
            reinterpret_cast<const ulonglong2*>(W_hh + (size_t)j * 128);
        #pragma unroll
        for (int k = 0; k < 32; ++k) {
            ulonglong2 v = wr[k];
            w2[2*k]   = v.x;
            w2[2*k+1] = v.y;
        }
    }

    const int off = g_off[b];
    const int end = (b == B_SEQ - 1) ? T : g_off[b + 1];
    const int len = end - off;

    if (j < 128) sh_h[j] = 0.f;
    __syncthreads();

    const float* xgp = g_xproj + (size_t)off * G3 + j;

    for (int t = 0; t < len; ++t) {
        // prefetch x-projection for this step (independent of h)
        float xg = xgp[(size_t)t * G3];

        // hg_j = dot(W_hh[j,:], h)  via packed f32x2
        const ulonglong2* hv = reinterpret_cast<const ulonglong2*>(sh_h);
        unsigned long long a0 = 0ull, a1 = 0ull, a2 = 0ull, a3 = 0ull;
        #pragma unroll
        for (int k = 0; k < 16; ++k) {
            ulonglong2 h0 = hv[2*k];
            ulonglong2 h1 = hv[2*k+1];
            ffma2(a0, w2[4*k+0], h0.x);
            ffma2(a1, w2[4*k+1], h0.y);
            ffma2(a2, w2[4*k+2], h1.x);
            ffma2(a3, w2[4*k+3], h1.y);
        }
        float hg = (unpack_sum(a0) + unpack_sum(a1)) +
                   (unpack_sum(a2) + unpack_sum(a3));

        sh_a[j] = xg + hg;
        if (j >= 256) sh_hgn[j - 256] = hg;
        __syncthreads();

        if (j < 128) {
            float r = 1.f / (1.f + expf(-sh_a[j]));
            float z = 1.f / (1.f + expf(-sh_a[j + 128]));
            // n = tanh(xg_n + r*hg_n) = tanh((xg_n + hg_n) + (r-1)*hg_n)
            float n = tanhf(sh_a[j + 256] + (r - 1.f) * sh_hgn[j]);
            sh_h[j] = (1.f - z) * n + z * sh_h[j];
        }
        __syncthreads();
    }

    // dense: v_j = dot(W_dense[j,:], h) + b_dense[j]
    float v = 0.f;
    if (j < 128) {
        const ulonglong2* wd =
            reinterpret_cast<const ulonglong2*>(W_dense + (size_t)j * 128);
        const ulonglong2* hv = reinterpret_cast<const ulonglong2*>(sh_h);
        unsigned long long a0 = 0ull, a1 = 0ull;
        #pragma unroll
        for (int k = 0; k < 16; ++k) {
            ulonglong2 wv = wd[2*k];
            ulonglong2 wu = wd[2*k+1];
            ulonglong2 h0 = hv[2*k];
            ulonglong2 h1 = hv[2*k+1];
            ffma2(a0, wv.x, h0.x);
            ffma2(a1, wv.y, h0.y);
            ffma2(a0, wu.x, h1.x);
            ffma2(a1, wu.y, h1.y);
        }
        v = unpack_sum(a0) + unpack_sum(a1) + b_dense[j];
        float s = v * v;
        #pragma unroll
        for (int d = 16; d > 0; d >>= 1)
            s += __shfl_xor_sync(0xffffffffu, s, d);
        if ((j & 31) == 0) sh_red[j >> 5] = s;
    }
    __syncthreads();
    if (j == 0) {
        float ss = sh_red[0] + sh_red[1] + sh_red[2] + sh_red[3];
        float nrm = fmaxf(sqrtf(ss), 1e-12f);
        sh_inv = 1.f / nrm;
    }
    __syncthreads();
    if (j < 128) out[(size_t)b * D_DIM + j] = v * sh_inv;
}

// ---------------------------------------------------------------------------
extern "C" void kernel_launch(void* const* d_in, const int* in_sizes, int n_in,
                              void* d_out, int out_size) {
    const float* x       = (const float*)d_in[0];
    const void*  off_raw = d_in[1];
    const float* W_ih    = (const float*)d_in[2];
    const float* W_hh    = (const float*)d_in[3];
    const float* W_dense = (const float*)d_in[4];
    const float* b_dense = (const float*)d_in[5];
    float* out = (float*)d_out;

    const int T = in_sizes[0] / D_DIM;

    offsets_kernel<<<2, 1024>>>(off_raw);

    const int nb = (T + XTILE - 1) / XTILE;
    xproj_kernel<<<nb, 384>>>(x, W_ih, T);

    gru_kernel<<<B_SEQ, 384>>>(W_hh, W_dense, b_dense, out, T);
}

// round 3
// speedup vs baseline: 1.1814x; 1.0479x over previous
#include <cuda_runtime.h>
#include <math.h>

#define B_SEQ   2048
#define D_DIM   128
#define H_DIM   128
#define G3      384            // 3*H
#define MAX_LEN 200
#define MAX_T   (B_SEQ * (MAX_LEN - 1))   // 407552 worst-case tokens

// Scratch for input projections x @ W_ih^T  : [T, 3H] fp32
__device__ float g_xproj[(size_t)MAX_T * G3];
// Normalized int32 offsets (handles int32 vs int64 input dtype)
__device__ int   g_off[B_SEQ];

// packed fp32x2 FMA: d = a*b + d
__device__ __forceinline__ void ffma2(unsigned long long& d,
                                      unsigned long long a,
                                      unsigned long long b) {
    asm volatile("fma.rn.f32x2 %0, %1, %2, %0;" : "+l"(d) : "l"(a), "l"(b));
}
__device__ __forceinline__ float unpack_sum(unsigned long long v) {
    unsigned int lo, hi;
    asm("mov.b64 {%0,%1}, %2;" : "=r"(lo), "=r"(hi) : "l"(v));
    return __uint_as_float(lo) + __uint_as_float(hi);
}

// ---------------------------------------------------------------------------
// Offset normalization (int32 vs int64 input dtype autodetect).
// ---------------------------------------------------------------------------
__global__ void offsets_kernel(const void* __restrict__ off_raw) {
    __shared__ int is64;
    const int* v32 = (const int*)off_raw;
    if (threadIdx.x == 0) {
        int f = 0;
        #pragma unroll
        for (int i = 0; i < 31; ++i) {
            if (v32[i + 1] < v32[i]) f = 1;
        }
        is64 = f;
    }
    __syncthreads();
    int gid = blockIdx.x * blockDim.x + threadIdx.x;
    if (gid < B_SEQ) {
        if (is64) {
            const long long* v64 = (const long long*)off_raw;
            g_off[gid] = (int)v64[gid];
        } else {
            g_off[gid] = v32[gid];
        }
    }
}

// ---------------------------------------------------------------------------
// Kernel 1: x_proj[t, j] = dot(W_ih[j, :], x[t, :])   for j in [0, 384)
// ---------------------------------------------------------------------------
#define XTILE 96
__global__ __launch_bounds__(384, 1)
void xproj_kernel(const float* __restrict__ x,
                  const float* __restrict__ W_ih, int T) {
    __shared__ __align__(16) float sx[XTILE * 128];
    const int j = threadIdx.x;

    unsigned long long w2[64];
    {
        const ulonglong2* wr =
            reinterpret_cast<const ulonglong2*>(W_ih + (size_t)j * 128);
        #pragma unroll
        for (int k = 0; k < 32; ++k) {
            ulonglong2 v = wr[k];
            w2[2*k]   = v.x;
            w2[2*k+1] = v.y;
        }
    }

    const int t0 = blockIdx.x * XTILE;
    const int ntok = min(XTILE, T - t0);
    if (ntok <= 0) return;

    const float4* xg = reinterpret_cast<const float4*>(x + (size_t)t0 * D_DIM);
    float4* sx4 = reinterpret_cast<float4*>(sx);
    for (int i = j; i < ntok * 32; i += 384) sx4[i] = xg[i];
    __syncthreads();

    float* outp = g_xproj + (size_t)t0 * G3 + j;
    for (int t = 0; t < ntok; ++t) {
        const ulonglong2* hv =
            reinterpret_cast<const ulonglong2*>(sx + t * D_DIM);
        unsigned long long a0 = 0ull, a1 = 0ull, a2 = 0ull, a3 = 0ull;
        #pragma unroll
        for (int k = 0; k < 16; ++k) {
            ulonglong2 h0 = hv[2*k];
            ulonglong2 h1 = hv[2*k+1];
            ffma2(a0, w2[4*k+0], h0.x);
            ffma2(a1, w2[4*k+1], h0.y);
            ffma2(a2, w2[4*k+2], h1.x);
            ffma2(a3, w2[4*k+3], h1.y);
        }
        outp[(size_t)t * G3] =
            (unpack_sum(a0) + unpack_sum(a1)) + (unpack_sum(a2) + unpack_sum(a3));
    }
}

// ---------------------------------------------------------------------------
// Kernel 2: ragged GRU recurrence, one block per sequence, 384 threads.
// Distance-2 register prefetch of the x-projection stream hides the
// per-step DRAM latency that the serial loop otherwise exposes.
// ---------------------------------------------------------------------------
__global__ __launch_bounds__(384, 1)
void gru_kernel(const float* __restrict__ W_hh,
                const float* __restrict__ W_dense,
                const float* __restrict__ b_dense,
                float* __restrict__ out, int T) {
    const int b = blockIdx.x;
    const int j = threadIdx.x;

    __shared__ __align__(16) float sh_h[128];     // hidden state
    __shared__ float sh_a[384];                   // xg + hg pre-activations
    __shared__ float sh_hgn[128];                 // hg for the n-gate
    __shared__ float sh_red[4];
    __shared__ float sh_inv;

    unsigned long long w2[64];
    {
        const ulonglong2* wr =
            reinterpret_cast<const ulonglong2*>(W_hh + (size_t)j * 128);
        #pragma unroll
        for (int k = 0; k < 32; ++k) {
            ulonglong2 v = wr[k];
            w2[2*k]   = v.x;
            w2[2*k+1] = v.y;
        }
    }

    const int off = g_off[b];
    const int end = (b == B_SEQ - 1) ? T : g_off[b + 1];
    const int len = end - off;

    if (j < 128) sh_h[j] = 0.f;
    __syncthreads();

    const float* xgp = g_xproj + (size_t)off * G3 + j;
    const int lm1 = len - 1;

    // distance-2 prefetch pipeline (clamped indices: always valid loads)
    float xg_cur = xgp[0];
    float xg_nxt = xgp[(size_t)min(1, lm1) * G3];

    for (int t = 0; t < len; ++t) {
        // issue the t+2 load NOW; consumed two iterations later
        float xg_pf = xgp[(size_t)min(t + 2, lm1) * G3];

        // hg_j = dot(W_hh[j,:], h)  via packed f32x2
        const ulonglong2* hv = reinterpret_cast<const ulonglong2*>(sh_h);
        unsigned long long a0 = 0ull, a1 = 0ull, a2 = 0ull, a3 = 0ull;
        #pragma unroll
        for (int k = 0; k < 16; ++k) {
            ulonglong2 h0 = hv[2*k];
            ulonglong2 h1 = hv[2*k+1];
            ffma2(a0, w2[4*k+0], h0.x);
            ffma2(a1, w2[4*k+1], h0.y);
            ffma2(a2, w2[4*k+2], h1.x);
            ffma2(a3, w2[4*k+3], h1.y);
        }
        float hg = (unpack_sum(a0) + unpack_sum(a1)) +
                   (unpack_sum(a2) + unpack_sum(a3));

        sh_a[j] = xg_cur + hg;
        if (j >= 256) sh_hgn[j - 256] = hg;
        __syncthreads();

        if (j < 128) {
            float r = 1.f / (1.f + expf(-sh_a[j]));
            float z = 1.f / (1.f + expf(-sh_a[j + 128]));
            float n = tanhf(sh_a[j + 256] + (r - 1.f) * sh_hgn[j]);
            sh_h[j] = (1.f - z) * n + z * sh_h[j];
        }
        __syncthreads();

        xg_cur = xg_nxt;
        xg_nxt = xg_pf;
    }

    // dense: v_j = dot(W_dense[j,:], h) + b_dense[j]
    float v = 0.f;
    if (j < 128) {
        const ulonglong2* wd =
            reinterpret_cast<const ulonglong2*>(W_dense + (size_t)j * 128);
        const ulonglong2* hv = reinterpret_cast<const ulonglong2*>(sh_h);
        unsigned long long a0 = 0ull, a1 = 0ull;
        #pragma unroll
        for (int k = 0; k < 16; ++k) {
            ulonglong2 wv = wd[2*k];
            ulonglong2 wu = wd[2*k+1];
            ulonglong2 h0 = hv[2*k];
            ulonglong2 h1 = hv[2*k+1];
            ffma2(a0, wv.x, h0.x);
            ffma2(a1, wv.y, h0.y);
            ffma2(a0, wu.x, h1.x);
            ffma2(a1, wu.y, h1.y);
        }
        v = unpack_sum(a0) + unpack_sum(a1) + b_dense[j];
        float s = v * v;
        #pragma unroll
        for (int d = 16; d > 0; d >>= 1)
            s += __shfl_xor_sync(0xffffffffu, s, d);
        if ((j & 31) == 0) sh_red[j >> 5] = s;
    }
    __syncthreads();
    if (j == 0) {
        float ss = sh_red[0] + sh_red[1] + sh_red[2] + sh_red[3];
        float nrm = fmaxf(sqrtf(ss), 1e-12f);
        sh_inv = 1.f / nrm;
    }
    __syncthreads();
    if (j < 128) out[(size_t)b * D_DIM + j] = v * sh_inv;
}

// ---------------------------------------------------------------------------
extern "C" void kernel_launch(void* const* d_in, const int* in_sizes, int n_in,
                              void* d_out, int out_size) {
    const float* x       = (const float*)d_in[0];
    const void*  off_raw = d_in[1];
    const float* W_ih    = (const float*)d_in[2];
    const float* W_hh    = (const float*)d_in[3];
    const float* W_dense = (const float*)d_in[4];
    const float* b_dense = (const float*)d_in[5];
    float* out = (float*)d_out;

    const int T = in_sizes[0] / D_DIM;

    offsets_kernel<<<2, 1024>>>(off_raw);

    const int nb = (T + XTILE - 1) / XTILE;
    xproj_kernel<<<nb, 384>>>(x, W_ih, T);

    gru_kernel<<<B_SEQ, 384>>>(W_hh, W_dense, b_dense, out, T);
}

// round 4
// speedup vs baseline: 1.4092x; 1.1929x over previous
#include <cuda_runtime.h>
#include <math.h>

#define B_SEQ   2048
#define D_DIM   128
#define H_DIM   128
#define G3      384            // 3*H
#define MAX_LEN 200
#define MAX_T   (B_SEQ * (MAX_LEN - 1))   // 407552 worst-case tokens
#define NSEQ    2              // sequences per GRU block

// Scratch for input projections x @ W_ih^T  : [T, 3H] fp32
__device__ float g_xproj[(size_t)MAX_T * G3];
__device__ int      g_off[B_SEQ];
__device__ unsigned g_order[B_SEQ];   // seq indices sorted by length desc

// packed fp32x2 FMA: d = a*b + d
__device__ __forceinline__ void ffma2(unsigned long long& d,
                                      unsigned long long a,
                                      unsigned long long b) {
    asm volatile("fma.rn.f32x2 %0, %1, %2, %0;" : "+l"(d) : "l"(a), "l"(b));
}
__device__ __forceinline__ float unpack_sum(unsigned long long v) {
    unsigned int lo, hi;
    asm("mov.b64 {%0,%1}, %2;" : "=r"(lo), "=r"(hi) : "l"(v));
    return __uint_as_float(lo) + __uint_as_float(hi);
}

// ---------------------------------------------------------------------------
// Offset normalization (int32 vs int64 input dtype autodetect).
// ---------------------------------------------------------------------------
__global__ void offsets_kernel(const void* __restrict__ off_raw) {
    __shared__ int is64;
    const int* v32 = (const int*)off_raw;
    if (threadIdx.x == 0) {
        int f = 0;
        #pragma unroll
        for (int i = 0; i < 31; ++i) {
            if (v32[i + 1] < v32[i]) f = 1;
        }
        is64 = f;
    }
    __syncthreads();
    int gid = blockIdx.x * blockDim.x + threadIdx.x;
    if (gid < B_SEQ) {
        if (is64) {
            const long long* v64 = (const long long*)off_raw;
            g_off[gid] = (int)v64[gid];
        } else {
            g_off[gid] = v32[gid];
        }
    }
}

// ---------------------------------------------------------------------------
// One-block bitonic sort of (length desc, idx) so equal-length sequences
// get paired and longest blocks launch first.
// key = (len << 11) | idx   (len < 256, idx < 2048)
// ---------------------------------------------------------------------------
__global__ void sort_kernel(int T) {
    __shared__ unsigned key[B_SEQ];
    const int tid = threadIdx.x;                 // 1024 threads
    for (int i = tid; i < B_SEQ; i += 1024) {
        int off = g_off[i];
        int end = (i == B_SEQ - 1) ? T : g_off[i + 1];
        key[i] = ((unsigned)(end - off) << 11) | (unsigned)i;
    }
    __syncthreads();
    for (int k = 2; k <= B_SEQ; k <<= 1) {
        for (int s = k >> 1; s > 0; s >>= 1) {
            for (int i = tid; i < B_SEQ; i += 1024) {
                int ixj = i ^ s;
                if (ixj > i) {
                    unsigned a = key[i], b = key[ixj];
                    bool seg_up = ((i & k) == 0);
                    // descending sort overall
                    if (seg_up ? (a < b) : (a > b)) { key[i] = b; key[ixj] = a; }
                }
            }
            __syncthreads();
        }
    }
    for (int i = tid; i < B_SEQ; i += 1024) g_order[i] = key[i] & 0x7FFu;
}

// ---------------------------------------------------------------------------
// Kernel 1: persistent x-projection. Grid = 148; weights loaded once/SM.
// ---------------------------------------------------------------------------
#define XTILE 96
__global__ __launch_bounds__(384, 1)
void xproj_kernel(const float* __restrict__ x,
                  const float* __restrict__ W_ih, int T) {
    __shared__ __align__(16) float sx[XTILE * 128];
    const int j = threadIdx.x;

    unsigned long long w2[64];
    {
        const ulonglong2* wr =
            reinterpret_cast<const ulonglong2*>(W_ih + (size_t)j * 128);
        #pragma unroll
        for (int k = 0; k < 32; ++k) {
            ulonglong2 v = wr[k];
            w2[2*k]   = v.x;
            w2[2*k+1] = v.y;
        }
    }

    const int ntiles = (T + XTILE - 1) / XTILE;
    for (int tile = blockIdx.x; tile < ntiles; tile += gridDim.x) {
        const int t0 = tile * XTILE;
        const int ntok = min(XTILE, T - t0);

        __syncthreads();   // previous iteration done reading sx
        const float4* xg = reinterpret_cast<const float4*>(x + (size_t)t0 * D_DIM);
        float4* sx4 = reinterpret_cast<float4*>(sx);
        for (int i = j; i < ntok * 32; i += 384) sx4[i] = xg[i];
        __syncthreads();

        float* outp = g_xproj + (size_t)t0 * G3 + j;
        for (int t = 0; t < ntok; ++t) {
            const ulonglong2* hv =
                reinterpret_cast<const ulonglong2*>(sx + t * D_DIM);
            unsigned long long a0 = 0ull, a1 = 0ull, a2 = 0ull, a3 = 0ull;
            #pragma unroll
            for (int k = 0; k < 16; ++k) {
                ulonglong2 h0 = hv[2*k];
                ulonglong2 h1 = hv[2*k+1];
                ffma2(a0, w2[4*k+0], h0.x);
                ffma2(a1, w2[4*k+1], h0.y);
                ffma2(a2, w2[4*k+2], h1.x);
                ffma2(a3, w2[4*k+3], h1.y);
            }
            outp[(size_t)t * G3] =
                (unpack_sum(a0) + unpack_sum(a1)) + (unpack_sum(a2) + unpack_sum(a3));
        }
    }
}

// ---------------------------------------------------------------------------
// Kernel 2: ragged GRU recurrence, 2 sequences per block (paired by length).
// ---------------------------------------------------------------------------
__global__ __launch_bounds__(384, 1)
void gru_kernel(const float* __restrict__ W_hh,
                const float* __restrict__ W_dense,
                const float* __restrict__ b_dense,
                float* __restrict__ out, int T) {
    const int j = threadIdx.x;

    __shared__ __align__(16) float sh_h[NSEQ][128];
    __shared__ float sh_a[NSEQ][384];
    __shared__ float sh_hgn[NSEQ][128];
    __shared__ float sh_red[NSEQ][4];
    __shared__ float sh_inv[NSEQ];
    __shared__ int   sh_meta[NSEQ * 3];       // off, len, sidx per seq

    unsigned long long w2[64];
    {
        const ulonglong2* wr =
            reinterpret_cast<const ulonglong2*>(W_hh + (size_t)j * 128);
        #pragma unroll
        for (int k = 0; k < 32; ++k) {
            ulonglong2 v = wr[k];
            w2[2*k]   = v.x;
            w2[2*k+1] = v.y;
        }
    }

    if (j < NSEQ) {
        int sidx = (int)g_order[blockIdx.x * NSEQ + j];
        int off  = g_off[sidx];
        int end  = (sidx == B_SEQ - 1) ? T : g_off[sidx + 1];
        sh_meta[3*j]     = off;
        sh_meta[3*j + 1] = end - off;
        sh_meta[3*j + 2] = sidx;
    }
    if (j < 128) { sh_h[0][j] = 0.f; sh_h[1][j] = 0.f; }
    __syncthreads();

    const int off0 = sh_meta[0], len0 = sh_meta[1];
    const int off1 = sh_meta[3], len1 = sh_meta[4];
    const int maxlen = max(len0, len1);
    const int l0 = len0 - 1, l1 = len1 - 1;

    const float* xgp0 = g_xproj + (size_t)off0 * G3 + j;
    const float* xgp1 = g_xproj + (size_t)off1 * G3 + j;

    float xg0c = xgp0[0];
    float xg1c = xgp1[0];
    float xg0n = xgp0[(size_t)min(1, l0) * G3];
    float xg1n = xgp1[(size_t)min(1, l1) * G3];

    for (int t = 0; t < maxlen; ++t) {
        float xg0p = xgp0[(size_t)min(t + 2, l0) * G3];
        float xg1p = xgp1[(size_t)min(t + 2, l1) * G3];

        // ---- dot for seq 0 ----
        {
            const ulonglong2* hv = reinterpret_cast<const ulonglong2*>(sh_h[0]);
            unsigned long long a0 = 0ull, a1 = 0ull, a2 = 0ull, a3 = 0ull;
            #pragma unroll
            for (int k = 0; k < 16; ++k) {
                ulonglong2 h0 = hv[2*k];
                ulonglong2 h1 = hv[2*k+1];
                ffma2(a0, w2[4*k+0], h0.x);
                ffma2(a1, w2[4*k+1], h0.y);
                ffma2(a2, w2[4*k+2], h1.x);
                ffma2(a3, w2[4*k+3], h1.y);
            }
            float hg = (unpack_sum(a0) + unpack_sum(a1)) +
                       (unpack_sum(a2) + unpack_sum(a3));
            sh_a[0][j] = xg0c + hg;
            if (j >= 256) sh_hgn[0][j - 256] = hg;
        }
        // ---- dot for seq 1 ----
        {
            const ulonglong2* hv = reinterpret_cast<const ulonglong2*>(sh_h[1]);
            unsigned long long a0 = 0ull, a1 = 0ull, a2 = 0ull, a3 = 0ull;
            #pragma unroll
            for (int k = 0; k < 16; ++k) {
                ulonglong2 h0 = hv[2*k];
                ulonglong2 h1 = hv[2*k+1];
                ffma2(a0, w2[4*k+0], h0.x);
                ffma2(a1, w2[4*k+1], h0.y);
                ffma2(a2, w2[4*k+2], h1.x);
                ffma2(a3, w2[4*k+3], h1.y);
            }
            float hg = (unpack_sum(a0) + unpack_sum(a1)) +
                       (unpack_sum(a2) + unpack_sum(a3));
            sh_a[1][j] = xg1c + hg;
            if (j >= 256) sh_hgn[1][j - 256] = hg;
        }
        __syncthreads();

        if (j < 256) {
            const int s    = j >> 7;
            const int lane = j & 127;
            const int len_s = s ? len1 : len0;
            if (t < len_s) {
                const float* a = sh_a[s];
                float r = 1.f / (1.f + expf(-a[lane]));
                float z = 1.f / (1.f + expf(-a[lane + 128]));
                float n = tanhf(a[lane + 256] + (r - 1.f) * sh_hgn[s][lane]);
                sh_h[s][lane] = (1.f - z) * n + z * sh_h[s][lane];
            }
        }
        __syncthreads();

        xg0c = xg0n; xg0n = xg0p;
        xg1c = xg1n; xg1n = xg1p;
    }

    // ---- epilogue: dense + L2-normalize, both sequences ----
    float v = 0.f;
    int s = 0, lane = 0;
    if (j < 256) {
        s = j >> 7; lane = j & 127;
        const ulonglong2* wd =
            reinterpret_cast<const ulonglong2*>(W_dense + (size_t)lane * 128);
        const ulonglong2* hv = reinterpret_cast<const ulonglong2*>(sh_h[s]);
        unsigned long long a0 = 0ull, a1 = 0ull;
        #pragma unroll
        for (int k = 0; k < 16; ++k) {
            ulonglong2 wv = wd[2*k];
            ulonglong2 wu = wd[2*k+1];
            ulonglong2 h0 = hv[2*k];
            ulonglong2 h1 = hv[2*k+1];
            ffma2(a0, wv.x, h0.x);
            ffma2(a1, wv.y, h0.y);
            ffma2(a0, wu.x, h1.x);
            ffma2(a1, wu.y, h1.y);
        }
        v = unpack_sum(a0) + unpack_sum(a1) + b_dense[lane];
        float sq = v * v;
        #pragma unroll
        for (int d = 16; d > 0; d >>= 1)
            sq += __shfl_xor_sync(0xffffffffu, sq, d);
        if ((lane & 31) == 0) sh_red[s][lane >> 5] = sq;
    }
    __syncthreads();
    if (j < NSEQ) {
        float ss = sh_red[j][0] + sh_red[j][1] + sh_red[j][2] + sh_red[j][3];
        sh_inv[j] = 1.f / fmaxf(sqrtf(ss), 1e-12f);
    }
    __syncthreads();
    if (j < 256) {
        const int sidx = sh_meta[3*s + 2];
        out[(size_t)sidx * D_DIM + lane] = v * sh_inv[s];
    }
}

// ---------------------------------------------------------------------------
extern "C" void kernel_launch(void* const* d_in, const int* in_sizes, int n_in,
                              void* d_out, int out_size) {
    const float* x       = (const float*)d_in[0];
    const void*  off_raw = d_in[1];
    const float* W_ih    = (const float*)d_in[2];
    const float* W_hh    = (const float*)d_in[3];
    const float* W_dense = (const float*)d_in[4];
    const float* b_dense = (const float*)d_in[5];
    float* out = (float*)d_out;

    const int T = in_sizes[0] / D_DIM;

    offsets_kernel<<<2, 1024>>>(off_raw);
    sort_kernel<<<1, 1024>>>(T);

    xproj_kernel<<<148, 384>>>(x, W_ih, T);

    gru_kernel<<<B_SEQ / NSEQ, 384>>>(W_hh, W_dense, b_dense, out, T);
}